// round 13
// baseline (speedup 1.0000x reference)
#include <cuda_runtime.h>
#include <cuda_bf16.h>
#include <cuda_fp16.h>
#include <math.h>
#include <float.h>

// Problem constants
#define Bq   4
#define Tq   16
#define Sq   4096
#define Hq   32
#define KVq  8
#define Dq   128
#define DIMq 4096
#define HD   (Hq*Dq)          // 4096
#define KVD  (KVq*Dq)         // 1024
#define NTOT (HD + 2*KVD)     // 6144
#define M64  (Bq*Tq)          // 64
#define GQ   (Hq/KVq)         // 4
#define AROWS 64
#define NSPLIT 13
#define SCALE_F 0.08838834764831843f
#define SPLITK  8             // qkv
#define SPLITKO 16            // out proj

// ---------------- scratch ----------------------------------------------------
__device__ float g_qkvp[SPLITK][M64 * NTOT];
__device__ float g_outp[SPLITKO][M64 * DIMq];
__device__ float g_qatt[Bq*KVq*AROWS*Dq];
__device__ float g_knew[M64*KVq*Dq];
__device__ float g_vnew[M64*KVD];
__device__ float g_pacc[(size_t)NSPLIT*Bq*KVq*AROWS*Dq];
__device__ float g_pm  [NSPLIT*Bq*KVq*AROWS];
__device__ float g_pl  [NSPLIT*Bq*KVq*AROWS];
__device__ float g_y   [M64 * HD];

// ================= shared helpers ===========================================
__device__ __forceinline__ unsigned smem_u32(const void* p) {
    unsigned a;
    asm("{ .reg .u64 t; cvta.to.shared.u64 t, %1; cvt.u32.u64 %0, t; }"
        : "=r"(a) : "l"(p));
    return a;
}
__device__ __forceinline__ unsigned f2tf32(float x) {
    unsigned u; asm("cvt.rna.tf32.f32 %0, %1;" : "=r"(u) : "f"(x)); return u;
}
__device__ __forceinline__ unsigned h2pack(float lo, float hi) {
    unsigned r; asm("cvt.rn.f16x2.f32 %0, %1, %2;" : "=r"(r) : "f"(hi), "f"(lo));
    return r;
}
__device__ __forceinline__ void mma_tf32(float c[4], const unsigned a[4], const unsigned b[2]) {
    asm volatile(
        "mma.sync.aligned.m16n8k8.row.col.f32.tf32.tf32.f32 "
        "{%0,%1,%2,%3}, {%4,%5,%6,%7}, {%8,%9}, {%0,%1,%2,%3};\n"
        : "+f"(c[0]), "+f"(c[1]), "+f"(c[2]), "+f"(c[3])
        : "r"(a[0]), "r"(a[1]), "r"(a[2]), "r"(a[3]), "r"(b[0]), "r"(b[1]));
}
__device__ __forceinline__ void mma_f16(float c[4], const unsigned a[4], const unsigned b[2]) {
    asm volatile(
        "mma.sync.aligned.m16n8k16.row.col.f32.f16.f16.f32 "
        "{%0,%1,%2,%3}, {%4,%5,%6,%7}, {%8,%9}, {%0,%1,%2,%3};\n"
        : "+f"(c[0]), "+f"(c[1]), "+f"(c[2]), "+f"(c[3])
        : "r"(a[0]), "r"(a[1]), "r"(a[2]), "r"(a[3]), "r"(b[0]), "r"(b[1]));
}
__device__ __forceinline__ void cpasync16(unsigned saddr, const void* g) {
    asm volatile("cp.async.ca.shared.global [%0], [%1], 16;" :: "r"(saddr), "l"(g));
}
__device__ __forceinline__ void sts32(unsigned baddr, unsigned v) {
    asm volatile("st.shared.u32 [%0], %1;" :: "r"(baddr), "r"(v));
}
__device__ __forceinline__ unsigned lds32(unsigned baddr) {
    unsigned x; asm volatile("ld.shared.u32 %0, [%1];" : "=r"(x) : "r"(baddr));
    return x;
}
__device__ __forceinline__ void lds64(unsigned &x, unsigned &y, unsigned baddr) {
    asm volatile("ld.shared.v2.u32 {%0, %1}, [%2];" : "=r"(x), "=r"(y) : "r"(baddr));
}
__device__ __forceinline__ float4 lds128f(unsigned baddr) {
    float4 v;
    asm volatile("ld.shared.v4.f32 {%0, %1, %2, %3}, [%4];"
                 : "=f"(v.x), "=f"(v.y), "=f"(v.z), "=f"(v.w) : "r"(baddr));
    return v;
}

// ================= tf32 split-K GEMM, 64x128 block tile, 3-stage ============
#define BKg      32
#define GSTAGES  3
#define GSTRIDE  36
#define GSTG_FLT (192 * GSTRIDE)
#define GEMM_SMEM_BYTES (GSTAGES * GSTG_FLT * 4)   // 82944
#define GK       4096

__device__ __forceinline__ void gemm_tile_mma(const float* __restrict__ A,
                                              const float* __restrict__ W,
                                              float* __restrict__ Cbase,
                                              int ldc, int kbeg, int nks) {
    extern __shared__ float smf[];
    const int tid  = threadIdx.x;
    const int lane = tid & 31;
    const int wid  = tid >> 5;
    const int gid  = lane >> 2;
    const int ctg  = lane & 3;
    const int wm   = wid & 1;
    const int wn   = wid >> 1;
    const int frA  = tid >> 2;
    const int fkA  = (tid & 3) * 8;
    const int frW  = tid >> 1;
    const int fkW  = (tid & 1) * 16;
    const unsigned sbase = smem_u32(smf);

    float acc[2][4][4];
#pragma unroll
    for (int mi = 0; mi < 2; mi++)
#pragma unroll
        for (int ni = 0; ni < 4; ni++)
#pragma unroll
            for (int j = 0; j < 4; j++) acc[mi][ni][j] = 0.f;

#pragma unroll
    for (int s = 0; s < GSTAGES - 1; s++) {
        unsigned sa = sbase + (unsigned)(s * GSTG_FLT + frA * GSTRIDE + fkA) * 4u;
        unsigned sw = sbase + (unsigned)(s * GSTG_FLT + (64 + frW) * GSTRIDE + fkW) * 4u;
        const float* ga = A + (size_t)frA * GK + kbeg + s * BKg + fkA;
        const float* gw = W + (size_t)frW * GK + kbeg + s * BKg + fkW;
        cpasync16(sa, ga);       cpasync16(sa + 16, ga + 4);
        cpasync16(sw, gw);       cpasync16(sw + 16, gw + 4);
        cpasync16(sw + 32, gw + 8); cpasync16(sw + 48, gw + 12);
        asm volatile("cp.async.commit_group;");
    }

    for (int i = 0; i < nks; i++) {
        asm volatile("cp.async.wait_group 1;");
        __syncthreads();
        int bufi = i % 3;
        const float* As = smf + bufi * GSTG_FLT;
        const float* Ws = As + 64 * GSTRIDE;

#pragma unroll
        for (int ks = 0; ks < 4; ks++) {
            const int k = ks * 8;
            unsigned af[2][4], bf[4][2];
#pragma unroll
            for (int mi = 0; mi < 2; mi++) {
                int r = wm * 32 + mi * 16 + gid;
                af[mi][0] = f2tf32(As[r * GSTRIDE + k + ctg]);
                af[mi][1] = f2tf32(As[(r + 8) * GSTRIDE + k + ctg]);
                af[mi][2] = f2tf32(As[r * GSTRIDE + k + ctg + 4]);
                af[mi][3] = f2tf32(As[(r + 8) * GSTRIDE + k + ctg + 4]);
            }
#pragma unroll
            for (int ni = 0; ni < 4; ni++) {
                int n = wn * 32 + ni * 8 + gid;
                bf[ni][0] = f2tf32(Ws[n * GSTRIDE + k + ctg]);
                bf[ni][1] = f2tf32(Ws[n * GSTRIDE + k + ctg + 4]);
            }
#pragma unroll
            for (int mi = 0; mi < 2; mi++)
#pragma unroll
                for (int ni = 0; ni < 4; ni++)
                    mma_tf32(acc[mi][ni], af[mi], bf[ni]);
        }

        if (i + GSTAGES - 1 < nks) {
            int s = (i + 2) % 3;
            int k0 = kbeg + (i + 2) * BKg;
            unsigned sa = sbase + (unsigned)(s * GSTG_FLT + frA * GSTRIDE + fkA) * 4u;
            unsigned sw = sbase + (unsigned)(s * GSTG_FLT + (64 + frW) * GSTRIDE + fkW) * 4u;
            const float* ga = A + (size_t)frA * GK + k0 + fkA;
            const float* gw = W + (size_t)frW * GK + k0 + fkW;
            cpasync16(sa, ga);       cpasync16(sa + 16, ga + 4);
            cpasync16(sw, gw);       cpasync16(sw + 16, gw + 4);
            cpasync16(sw + 32, gw + 8); cpasync16(sw + 48, gw + 12);
            asm volatile("cp.async.commit_group;");
        } else {
            asm volatile("cp.async.commit_group;");
        }
    }

#pragma unroll
    for (int mi = 0; mi < 2; mi++)
#pragma unroll
        for (int ni = 0; ni < 4; ni++) {
            int r0 = wm * 32 + mi * 16 + gid;
            int c0 = wn * 32 + ni * 8 + 2 * ctg;
            *reinterpret_cast<float2*>(&Cbase[(size_t)r0 * ldc + c0]) =
                make_float2(acc[mi][ni][0], acc[mi][ni][1]);
            *reinterpret_cast<float2*>(&Cbase[(size_t)(r0 + 8) * ldc + c0]) =
                make_float2(acc[mi][ni][2], acc[mi][ni][3]);
        }
}

__global__ void qkv_kernel(const float* __restrict__ x,
                           const float* __restrict__ wq,
                           const float* __restrict__ wk,
                           const float* __restrict__ wv) {
    int n0 = blockIdx.x * 128;
    int sp = blockIdx.y;
    const float* W;
    if (n0 < HD)            W = wq + (size_t)n0 * DIMq;
    else if (n0 < HD + KVD) W = wk + (size_t)(n0 - HD) * DIMq;
    else                    W = wv + (size_t)(n0 - HD - KVD) * DIMq;
    gemm_tile_mma(x, W, g_qkvp[sp] + n0, NTOT, sp * (GK / SPLITK), GK / BKg / SPLITK);
}

__global__ void out_kernel(const float* __restrict__ wo) {
    int n0 = blockIdx.x * 128;
    int sp = blockIdx.y;
    gemm_tile_mma(g_y, wo + (size_t)n0 * DIMq, g_outp[sp] + n0, DIMq,
                  sp * (GK / SPLITKO), GK / BKg / SPLITKO);
}

__global__ void reduce_out_kernel(float* __restrict__ out) {
    int i = blockIdx.x * 256 + threadIdx.x;
    if (i >= M64 * DIMq / 4) return;
    float4 r = reinterpret_cast<const float4*>(g_outp[0])[i];
#pragma unroll
    for (int sp = 1; sp < SPLITKO; sp++) {
        float4 v = reinterpret_cast<const float4*>(g_outp[sp])[i];
        r.x += v.x; r.y += v.y; r.z += v.z; r.w += v.w;
    }
    reinterpret_cast<float4*>(out)[i] = r;
}

// ---------------- fused split-K reduce + RoPE (two kernels) ------------------
#define QPAIRS (M64*Hq*(Dq/2))   // 131072
#define KPAIRS (M64*KVq*(Dq/2))  // 32768
#define VQUADS (M64*KVD/4)       // 16384
__global__ void rope_q_kernel(const float* __restrict__ fc,
                              const float* __restrict__ fs) {
    int idx = blockIdx.x * blockDim.x + threadIdx.x;
    if (idx >= QPAIRS) return;
    int i = idx & 63;
    int h = (idx >> 6) & (Hq - 1);
    int m = idx >> 11;
    int t = m & (Tq - 1), b = m >> 4;
    size_t off = (size_t)m * NTOT + h * Dq + 2 * i;
    float x0 = 0.f, x1 = 0.f;
#pragma unroll
    for (int sp = 0; sp < SPLITK; sp++) {
        float2 p = *reinterpret_cast<const float2*>(&g_qkvp[sp][off]);
        x0 += p.x; x1 += p.y;
    }
    float c = fc[t * 64 + i], s = fs[t * 64 + i];
    int kv = h >> 2, hl = h & 3;
    float* q = g_qatt + ((((size_t)b * KVq + kv) * AROWS) + hl * Tq + t) * Dq + 2 * i;
    q[0] = (x0 * c - x1 * s) * SCALE_F;
    q[1] = (x0 * s + x1 * c) * SCALE_F;
}

__global__ void rope_kv_kernel(const float* __restrict__ fc,
                               const float* __restrict__ fs) {
    int idx = blockIdx.x * blockDim.x + threadIdx.x;
    if (idx < KPAIRS) {
        int i = idx & 63;
        int kv = (idx >> 6) & (KVq - 1);
        int m = idx >> 9;
        int t = m & (Tq - 1);
        size_t off = (size_t)m * NTOT + HD + kv * Dq + 2 * i;
        float x0 = 0.f, x1 = 0.f;
#pragma unroll
        for (int sp = 0; sp < SPLITK; sp++) {
            float2 p = *reinterpret_cast<const float2*>(&g_qkvp[sp][off]);
            x0 += p.x; x1 += p.y;
        }
        float c = fc[t * 64 + i], s = fs[t * 64 + i];
        float* k = g_knew + ((size_t)m * KVq + kv) * Dq + 2 * i;
        k[0] = x0 * c - x1 * s;
        k[1] = x0 * s + x1 * c;
    } else if (idx < KPAIRS + VQUADS) {
        int j = idx - KPAIRS;
        int m = j >> 8;
        int c4 = (j & 255) * 4;
        size_t off = (size_t)m * NTOT + HD + KVD + c4;
        float4 r = make_float4(0.f, 0.f, 0.f, 0.f);
#pragma unroll
        for (int sp = 0; sp < SPLITK; sp++) {
            float4 v = *reinterpret_cast<const float4*>(&g_qkvp[sp][off]);
            r.x += v.x; r.y += v.y; r.z += v.z; r.w += v.w;
        }
        *reinterpret_cast<float4*>(&g_vnew[(size_t)m * KVD + c4]) = r;
    }
}

// ================= tensor-core flash attention v7 ===========================
// cp.async raw-fp32 staging (no prefetch regs) + smem convert to packed fp16.
// 128 threads / 4 warps, warp owns 16 q-rows x 32 keys; 3 blocks/SM.
#define KV_TILE 32
#define RAWS  132                            // raw row stride (floats)
#define KROWW 72                             // packed K row stride (words)
#define VROWW 136                            // packed V pair-row stride (words)
#define RAWK_W 0
#define RAWV_W (32 * RAWS)                   // 4224
#define PKK_W  (2 * 32 * RAWS)               // 8448
#define PKV_W  (PKK_W + 32 * KROWW)          // 10752
#define ATTN_SMEM_W (PKV_W + 16 * VROWW)     // 12928 words
#define ATTN_SMEM_BYTES (ATTN_SMEM_W * 4)    // 51712

__global__ void __launch_bounds__(128, 3)
attn_kernel(const float* __restrict__ k_cache,
            const float* __restrict__ v_cache,
            const int* __restrict__ input_pos) {
    extern __shared__ float smA[];
    __shared__ int pos_s[Tq];

    const int tid  = threadIdx.x;
    const int lane = tid & 31;
    const int gid  = lane >> 2;
    const int ctg  = lane & 3;
    const int wid  = tid >> 5;
    const int r0   = wid * 16 + gid;

    const int bk = blockIdx.x & 31;
    const int split = blockIdx.x >> 5;
    const int b = bk >> 3, kv = bk & 7;

    if (tid < Tq) pos_s[tid] = input_pos[tid];

    const int start_pos = __ldg(&input_pos[0]);
    const int limit = __ldg(&input_pos[Tq - 1]) + 1;
    const int totalTiles = (limit + KV_TILE - 1) / KV_TILE;
    const int tbase = totalTiles / NSPLIT, trem = totalTiles % NSPLIT;
    const int t0 = split * tbase + min(split, trem);
    const int tcount = tbase + (split < trem);
    const int sbeg = t0 * KV_TILE;
    const int send = min((t0 + tcount) * KV_TILE, limit);

    // ---- Q into fp16 registers: 8 k16-chunks x 4 regs ----
    unsigned qreg[8][4];
    {
        const float* qa = g_qatt + (((size_t)b * KVq + kv) * AROWS + r0) * Dq;
        const float* qb = qa + 8 * Dq;
#pragma unroll
        for (int ks = 0; ks < 8; ks++) {
            int c0 = ks * 16 + 2 * ctg;
            qreg[ks][0] = h2pack(qa[c0],     qa[c0 + 1]);
            qreg[ks][1] = h2pack(qb[c0],     qb[c0 + 1]);
            qreg[ks][2] = h2pack(qa[c0 + 8], qa[c0 + 9]);
            qreg[ks][3] = h2pack(qb[c0 + 8], qb[c0 + 9]);
        }
    }

    const unsigned sb   = smem_u32(smA);
    const unsigned rawK = sb;
    const unsigned rawV = sb + RAWV_W * 4u;
    const unsigned pkK  = sb + PKK_W * 4u;
    const unsigned pkV  = sb + PKV_W * 4u;

    // ---- cp.async fill: thread -> row tid>>2, 32-float segment (tid&3) ----
    const int fr  = tid >> 2;
    const int fs4 = (tid & 3) * 32;

    auto row_ptr_k = [&](int s) -> const float* {
        if (s >= start_pos && s < start_pos + Tq)
            return &g_knew[((size_t)(b * Tq + (s - start_pos)) * KVq + kv) * Dq];
        return &k_cache[(((size_t)b * Sq + s) * KVq + kv) * Dq];
    };
    auto row_ptr_v = [&](int s) -> const float* {
        if (s >= start_pos && s < start_pos + Tq)
            return &g_vnew[(size_t)(b * Tq + (s - start_pos)) * KVD + kv * Dq];
        return &v_cache[(((size_t)b * Sq + s) * KVq + kv) * Dq];
    };

    auto issue_raw = [&](int s0t) {
        int s = s0t + fr;
        const float* kp = row_ptr_k(s) + fs4;
        const float* vp = row_ptr_v(s) + fs4;
        unsigned kd = rawK + (unsigned)(fr * RAWS + fs4) * 4u;
        unsigned vd = rawV + (unsigned)(fr * RAWS + fs4) * 4u;
#pragma unroll
        for (int j = 0; j < 8; j++) {
            cpasync16(kd + j * 16u, kp + j * 4);
            cpasync16(vd + j * 16u, vp + j * 4);
        }
    };

    // ---- convert raw -> packed ----
    const int cr = tid & 31;          // K row
    const int cq = tid >> 5;          // K 32-float chunk (0..3)
    const int vp2 = tid & 15;         // V pair-row
    const int vcq = tid >> 4;         // V 16-float chunk (0..7)

    auto convert_tile = [&]() {
        // K: row cr, chunk cq -> k16 chunks ks = 2cq, 2cq+1
        float4 kf[8];
#pragma unroll
        for (int j = 0; j < 8; j++)
            kf[j] = lds128f(rawK + (unsigned)(cr * RAWS + cq * 32 + j * 4) * 4u);
#pragma unroll
        for (int ks = 0; ks < 2; ks++) {
            unsigned cb = pkK + (unsigned)(cr * KROWW) * 4u + (2 * cq + ks) * 32u;
#pragma unroll
            for (int c = 0; c < 8; c++) {
                float4 f = kf[ks * 4 + (c >> 1)];
                float lo = (c & 1) ? f.z : f.x;
                float hi = (c & 1) ? f.w : f.y;
                sts32(cb + (unsigned)((c & 3) * 8 + (c >> 2) * 4), h2pack(lo, hi));
            }
        }
        // V: pair-row vp2, d in [vcq*16, vcq*16+16)
        int vdb = vcq * 16;
        float4 a0[4], a1[4];
#pragma unroll
        for (int j = 0; j < 4; j++) {
            a0[j] = lds128f(rawV + (unsigned)((2 * vp2) * RAWS + vdb + j * 4) * 4u);
            a1[j] = lds128f(rawV + (unsigned)((2 * vp2 + 1) * RAWS + vdb + j * 4) * 4u);
        }
        unsigned vb = pkV + (unsigned)(vp2 * VROWW + vdb) * 4u;
#pragma unroll
        for (int j = 0; j < 4; j++) {
            sts32(vb + (unsigned)(j * 4 + 0) * 4u, h2pack(a0[j].x, a1[j].x));
            sts32(vb + (unsigned)(j * 4 + 1) * 4u, h2pack(a0[j].y, a1[j].y));
            sts32(vb + (unsigned)(j * 4 + 2) * 4u, h2pack(a0[j].z, a1[j].z));
            sts32(vb + (unsigned)(j * 4 + 3) * 4u, h2pack(a0[j].w, a1[j].w));
        }
    };

    if (tcount > 0) issue_raw(sbeg);
    asm volatile("cp.async.commit_group;");

    float acc[16][4];
#pragma unroll
    for (int nt = 0; nt < 16; nt++)
#pragma unroll
        for (int j = 0; j < 4; j++) acc[nt][j] = 0.f;
    float m0 = -FLT_MAX, m1 = -FLT_MAX, l0 = 0.f, l1 = 0.f;

    for (int t = 0; t < tcount; t++) {
        const int s0 = sbeg + t * KV_TILE;
        asm volatile("cp.async.wait_group 0;");
        __syncthreads();                 // raw ready; prev compute done
        convert_tile();
        __syncthreads();                 // packed ready; raw consumed
        if (t + 1 < tcount) issue_raw(s0 + KV_TILE);
        asm volatile("cp.async.commit_group;");

        // ---- QK^T: 16 rows x 32 keys, fp16 k16 steps ----
        float sc[4][4];
#pragma unroll
        for (int nt = 0; nt < 4; nt++)
#pragma unroll
            for (int j = 0; j < 4; j++) sc[nt][j] = 0.f;
#pragma unroll
        for (int ks = 0; ks < 8; ks++) {
#pragma unroll
            for (int nt = 0; nt < 4; nt++) {
                int key = nt * 8 + gid;
                unsigned bfr[2];
                lds64(bfr[0], bfr[1],
                      pkK + (unsigned)(key * KROWW) * 4u + (unsigned)(ks * 32 + ctg * 8));
                mma_f16(sc[nt], qreg[ks], bfr);
            }
        }

        // ---- mask + warp-local online softmax ----
        const int p0 = pos_s[gid];
        const int p1 = pos_s[gid + 8];
        float tm0 = -FLT_MAX, tm1 = -FLT_MAX;
#pragma unroll
        for (int nt = 0; nt < 4; nt++) {
            int cb = nt * 8 + 2 * ctg;
            int sA = s0 + cb, sB = sA + 1;
            sc[nt][0] = (sA < send && sA <= p0) ? sc[nt][0] : -FLT_MAX;
            sc[nt][1] = (sB < send && sB <= p0) ? sc[nt][1] : -FLT_MAX;
            sc[nt][2] = (sA < send && sA <= p1) ? sc[nt][2] : -FLT_MAX;
            sc[nt][3] = (sB < send && sB <= p1) ? sc[nt][3] : -FLT_MAX;
            tm0 = fmaxf(tm0, fmaxf(sc[nt][0], sc[nt][1]));
            tm1 = fmaxf(tm1, fmaxf(sc[nt][2], sc[nt][3]));
        }
        tm0 = fmaxf(tm0, __shfl_xor_sync(0xFFFFFFFF, tm0, 1));
        tm0 = fmaxf(tm0, __shfl_xor_sync(0xFFFFFFFF, tm0, 2));
        tm1 = fmaxf(tm1, __shfl_xor_sync(0xFFFFFFFF, tm1, 1));
        tm1 = fmaxf(tm1, __shfl_xor_sync(0xFFFFFFFF, tm1, 2));
        float mn0 = fmaxf(m0, tm0), mn1 = fmaxf(m1, tm1);
        float scl0 = __expf(m0 - mn0), scl1 = __expf(m1 - mn1);

        unsigned ps[4][2];
        float su0 = 0.f, su1 = 0.f;
#pragma unroll
        for (int nt = 0; nt < 4; nt++) {
            float e0 = __expf(sc[nt][0] - mn0), e1 = __expf(sc[nt][1] - mn0);
            float e2 = __expf(sc[nt][2] - mn1), e3 = __expf(sc[nt][3] - mn1);
            ps[nt][0] = h2pack(e0, e1);
            ps[nt][1] = h2pack(e2, e3);
            float2 f0 = __half22float2(*reinterpret_cast<__half2*>(&ps[nt][0]));
            float2 f1 = __half22float2(*reinterpret_cast<__half2*>(&ps[nt][1]));
            su0 += f0.x + f0.y;
            su1 += f1.x + f1.y;
        }
        su0 += __shfl_xor_sync(0xFFFFFFFF, su0, 1);
        su0 += __shfl_xor_sync(0xFFFFFFFF, su0, 2);
        su1 += __shfl_xor_sync(0xFFFFFFFF, su1, 1);
        su1 += __shfl_xor_sync(0xFFFFFFFF, su1, 2);
        l0 = l0 * scl0 + su0;
        l1 = l1 * scl1 + su1;
        m0 = mn0; m1 = mn1;

        // ---- rescale ----
#pragma unroll
        for (int nt = 0; nt < 16; nt++) {
            acc[nt][0] *= scl0; acc[nt][1] *= scl0;
            acc[nt][2] *= scl1; acc[nt][3] *= scl1;
        }

        // ---- P@V: C-frag == A-frag (no shfl), V fragments via LDS.32 ----
#pragma unroll
        for (int kt = 0; kt < 2; kt++) {
            unsigned a[4];
            a[0] = ps[2 * kt][0];
            a[1] = ps[2 * kt][1];
            a[2] = ps[2 * kt + 1][0];
            a[3] = ps[2 * kt + 1][1];
#pragma unroll
            for (int nt = 0; nt < 16; nt++) {
                int n = nt * 8 + gid;
                unsigned bfr[2];
                bfr[0] = lds32(pkV + (unsigned)((8 * kt + ctg) * VROWW + n) * 4u);
                bfr[1] = lds32(pkV + (unsigned)((8 * kt + ctg + 4) * VROWW + n) * 4u);
                mma_f16(acc[nt], a, bfr);
            }
        }
    }

    // ---- write split partials ----
    {
        float* pbase = g_pacc + ((size_t)split * Bq * KVq + bk) * AROWS * Dq;
#pragma unroll
        for (int nt = 0; nt < 16; nt++) {
            int col = nt * 8 + 2 * ctg;
            *reinterpret_cast<float2*>(&pbase[(size_t)r0 * Dq + col]) =
                make_float2(acc[nt][0], acc[nt][1]);
            *reinterpret_cast<float2*>(&pbase[(size_t)(r0 + 8) * Dq + col]) =
                make_float2(acc[nt][2], acc[nt][3]);
        }
    }
    if (ctg == 0) {
        int o = (split * Bq * KVq + bk) * AROWS;
        g_pm[o + r0] = m0;      g_pl[o + r0] = l0;
        g_pm[o + r0 + 8] = m1;  g_pl[o + r0 + 8] = l1;
    }
}

// ---------------- combine splits --------------------------------------------
__global__ void combine_kernel() {
    int idx = blockIdx.x * 256 + threadIdx.x;
    if (idx >= Bq * KVq * AROWS * Dq) return;
    int d = idx & 127;
    int r = (idx >> 7) & 63;
    int bk = idx >> 13;
    float M = -FLT_MAX;
#pragma unroll
    for (int sp = 0; sp < NSPLIT; sp++)
        M = fmaxf(M, g_pm[(sp * Bq * KVq + bk) * AROWS + r]);
    float L = 0.f, Y = 0.f;
#pragma unroll
    for (int sp = 0; sp < NSPLIT; sp++) {
        int o = (sp * Bq * KVq + bk) * AROWS + r;
        float w = __expf(g_pm[o] - M);
        L += g_pl[o] * w;
        Y += g_pacc[(size_t)o * Dq + d] * w;
    }
    float y = Y / L;
    int b = bk >> 3, kv = bk & 7;
    int hl = r >> 4, t = r & 15;
    int h = kv * GQ + hl;
    int m = b * Tq + t;
    g_y[(size_t)m * HD + h * Dq + d] = y;
}

// ---------------- launch -----------------------------------------------------
extern "C" void kernel_launch(void* const* d_in, const int* in_sizes, int n_in,
                              void* d_out, int out_size) {
    const float* x  = (const float*)d_in[0];
    const float* fc = (const float*)d_in[1];
    const float* fs = (const float*)d_in[2];
    const int*  pos = (const int*)  d_in[3];
    const float* kc = (const float*)d_in[5];
    const float* vc = (const float*)d_in[6];
    const float* wq = (const float*)d_in[7];
    const float* wk = (const float*)d_in[8];
    const float* wv = (const float*)d_in[9];
    const float* wo = (const float*)d_in[10];
    float* out = (float*)d_out;

    cudaFuncSetAttribute(qkv_kernel, cudaFuncAttributeMaxDynamicSharedMemorySize,
                         GEMM_SMEM_BYTES);
    cudaFuncSetAttribute(out_kernel, cudaFuncAttributeMaxDynamicSharedMemorySize,
                         GEMM_SMEM_BYTES);
    cudaFuncSetAttribute(attn_kernel, cudaFuncAttributeMaxDynamicSharedMemorySize,
                         ATTN_SMEM_BYTES);

    qkv_kernel<<<dim3(NTOT / 128, SPLITK), 256, GEMM_SMEM_BYTES>>>(x, wq, wk, wv);
    rope_q_kernel<<<(QPAIRS + 255) / 256, 256>>>(fc, fs);
    rope_kv_kernel<<<(KPAIRS + VQUADS + 255) / 256, 256>>>(fc, fs);
    attn_kernel<<<NSPLIT * Bq * KVq, 128, ATTN_SMEM_BYTES>>>(kc, vc, pos);
    combine_kernel<<<(Bq * KVq * AROWS * Dq + 255) / 256, 256>>>();
    out_kernel<<<dim3(DIMq / 128, SPLITKO), 256, GEMM_SMEM_BYTES>>>(wo);
    reduce_out_kernel<<<(M64 * DIMq / 4 + 255) / 256, 256>>>(out);
}

// round 14
// speedup vs baseline: 1.1111x; 1.1111x over previous
#include <cuda_runtime.h>
#include <cuda_bf16.h>
#include <cuda_fp16.h>
#include <math.h>
#include <float.h>

// Problem constants
#define Bq   4
#define Tq   16
#define Sq   4096
#define Hq   32
#define KVq  8
#define Dq   128
#define DIMq 4096
#define HD   (Hq*Dq)          // 4096
#define KVD  (KVq*Dq)         // 1024
#define NTOT (HD + 2*KVD)     // 6144
#define M64  (Bq*Tq)          // 64
#define GQ   (Hq/KVq)         // 4
#define AROWS 64
#define NSPLIT 9
#define SCALE_F 0.08838834764831843f
#define SPLITK  8             // qkv
#define SPLITKO 16            // out proj

// ---------------- scratch ----------------------------------------------------
__device__ float g_qkvp[SPLITK][M64 * NTOT];
__device__ float g_outp[SPLITKO][M64 * DIMq];
__device__ float g_qatt[Bq*KVq*AROWS*Dq];
__device__ float g_knew[M64*KVq*Dq];
__device__ float g_vnew[M64*KVD];
__device__ float g_pacc[(size_t)NSPLIT*Bq*KVq*AROWS*Dq];
__device__ float g_pm  [NSPLIT*Bq*KVq*AROWS];
__device__ float g_pl  [NSPLIT*Bq*KVq*AROWS];
__device__ float g_y   [M64 * HD];

// ================= shared helpers ===========================================
__device__ __forceinline__ unsigned smem_u32(const void* p) {
    unsigned a;
    asm("{ .reg .u64 t; cvta.to.shared.u64 t, %1; cvt.u32.u64 %0, t; }"
        : "=r"(a) : "l"(p));
    return a;
}
__device__ __forceinline__ unsigned f2tf32(float x) {
    unsigned u; asm("cvt.rna.tf32.f32 %0, %1;" : "=r"(u) : "f"(x)); return u;
}
__device__ __forceinline__ unsigned h2pack(float lo, float hi) {
    unsigned r; asm("cvt.rn.f16x2.f32 %0, %1, %2;" : "=r"(r) : "f"(hi), "f"(lo));
    return r;
}
__device__ __forceinline__ void mma_tf32(float c[4], const unsigned a[4], const unsigned b[2]) {
    asm volatile(
        "mma.sync.aligned.m16n8k8.row.col.f32.tf32.tf32.f32 "
        "{%0,%1,%2,%3}, {%4,%5,%6,%7}, {%8,%9}, {%0,%1,%2,%3};\n"
        : "+f"(c[0]), "+f"(c[1]), "+f"(c[2]), "+f"(c[3])
        : "r"(a[0]), "r"(a[1]), "r"(a[2]), "r"(a[3]), "r"(b[0]), "r"(b[1]));
}
__device__ __forceinline__ void mma_f16(float c[4], const unsigned a[4], const unsigned b[2]) {
    asm volatile(
        "mma.sync.aligned.m16n8k16.row.col.f32.f16.f16.f32 "
        "{%0,%1,%2,%3}, {%4,%5,%6,%7}, {%8,%9}, {%0,%1,%2,%3};\n"
        : "+f"(c[0]), "+f"(c[1]), "+f"(c[2]), "+f"(c[3])
        : "r"(a[0]), "r"(a[1]), "r"(a[2]), "r"(a[3]), "r"(b[0]), "r"(b[1]));
}
__device__ __forceinline__ void cpasync16(unsigned saddr, const void* g) {
    asm volatile("cp.async.ca.shared.global [%0], [%1], 16;" :: "r"(saddr), "l"(g));
}
__device__ __forceinline__ void sts32(unsigned baddr, unsigned v) {
    asm volatile("st.shared.u32 [%0], %1;" :: "r"(baddr), "r"(v));
}
__device__ __forceinline__ unsigned lds32(unsigned baddr) {
    unsigned x; asm volatile("ld.shared.u32 %0, [%1];" : "=r"(x) : "r"(baddr));
    return x;
}
__device__ __forceinline__ void lds64(unsigned &x, unsigned &y, unsigned baddr) {
    asm volatile("ld.shared.v2.u32 {%0, %1}, [%2];" : "=r"(x), "=r"(y) : "r"(baddr));
}

// ================= tf32 split-K GEMM, 64x128 block tile, 3-stage ============
#define BKg      32
#define GSTAGES  3
#define GSTRIDE  36
#define GSTG_FLT (192 * GSTRIDE)
#define GEMM_SMEM_BYTES (GSTAGES * GSTG_FLT * 4)   // 82944
#define GK       4096

__device__ __forceinline__ void gemm_tile_mma(const float* __restrict__ A,
                                              const float* __restrict__ W,
                                              float* __restrict__ Cbase,
                                              int ldc, int kbeg, int nks) {
    extern __shared__ float smf[];
    const int tid  = threadIdx.x;
    const int lane = tid & 31;
    const int wid  = tid >> 5;
    const int gid  = lane >> 2;
    const int ctg  = lane & 3;
    const int wm   = wid & 1;
    const int wn   = wid >> 1;
    const int frA  = tid >> 2;
    const int fkA  = (tid & 3) * 8;
    const int frW  = tid >> 1;
    const int fkW  = (tid & 1) * 16;
    const unsigned sbase = smem_u32(smf);

    float acc[2][4][4];
#pragma unroll
    for (int mi = 0; mi < 2; mi++)
#pragma unroll
        for (int ni = 0; ni < 4; ni++)
#pragma unroll
            for (int j = 0; j < 4; j++) acc[mi][ni][j] = 0.f;

#pragma unroll
    for (int s = 0; s < GSTAGES - 1; s++) {
        unsigned sa = sbase + (unsigned)(s * GSTG_FLT + frA * GSTRIDE + fkA) * 4u;
        unsigned sw = sbase + (unsigned)(s * GSTG_FLT + (64 + frW) * GSTRIDE + fkW) * 4u;
        const float* ga = A + (size_t)frA * GK + kbeg + s * BKg + fkA;
        const float* gw = W + (size_t)frW * GK + kbeg + s * BKg + fkW;
        cpasync16(sa, ga);       cpasync16(sa + 16, ga + 4);
        cpasync16(sw, gw);       cpasync16(sw + 16, gw + 4);
        cpasync16(sw + 32, gw + 8); cpasync16(sw + 48, gw + 12);
        asm volatile("cp.async.commit_group;");
    }

    for (int i = 0; i < nks; i++) {
        asm volatile("cp.async.wait_group 1;");
        __syncthreads();
        int bufi = i % 3;
        const float* As = smf + bufi * GSTG_FLT;
        const float* Ws = As + 64 * GSTRIDE;

#pragma unroll
        for (int ks = 0; ks < 4; ks++) {
            const int k = ks * 8;
            unsigned af[2][4], bf[4][2];
#pragma unroll
            for (int mi = 0; mi < 2; mi++) {
                int r = wm * 32 + mi * 16 + gid;
                af[mi][0] = f2tf32(As[r * GSTRIDE + k + ctg]);
                af[mi][1] = f2tf32(As[(r + 8) * GSTRIDE + k + ctg]);
                af[mi][2] = f2tf32(As[r * GSTRIDE + k + ctg + 4]);
                af[mi][3] = f2tf32(As[(r + 8) * GSTRIDE + k + ctg + 4]);
            }
#pragma unroll
            for (int ni = 0; ni < 4; ni++) {
                int n = wn * 32 + ni * 8 + gid;
                bf[ni][0] = f2tf32(Ws[n * GSTRIDE + k + ctg]);
                bf[ni][1] = f2tf32(Ws[n * GSTRIDE + k + ctg + 4]);
            }
#pragma unroll
            for (int mi = 0; mi < 2; mi++)
#pragma unroll
                for (int ni = 0; ni < 4; ni++)
                    mma_tf32(acc[mi][ni], af[mi], bf[ni]);
        }

        if (i + GSTAGES - 1 < nks) {
            int s = (i + 2) % 3;
            int k0 = kbeg + (i + 2) * BKg;
            unsigned sa = sbase + (unsigned)(s * GSTG_FLT + frA * GSTRIDE + fkA) * 4u;
            unsigned sw = sbase + (unsigned)(s * GSTG_FLT + (64 + frW) * GSTRIDE + fkW) * 4u;
            const float* ga = A + (size_t)frA * GK + k0 + fkA;
            const float* gw = W + (size_t)frW * GK + k0 + fkW;
            cpasync16(sa, ga);       cpasync16(sa + 16, ga + 4);
            cpasync16(sw, gw);       cpasync16(sw + 16, gw + 4);
            cpasync16(sw + 32, gw + 8); cpasync16(sw + 48, gw + 12);
            asm volatile("cp.async.commit_group;");
        } else {
            asm volatile("cp.async.commit_group;");
        }
    }

#pragma unroll
    for (int mi = 0; mi < 2; mi++)
#pragma unroll
        for (int ni = 0; ni < 4; ni++) {
            int r0 = wm * 32 + mi * 16 + gid;
            int c0 = wn * 32 + ni * 8 + 2 * ctg;
            *reinterpret_cast<float2*>(&Cbase[(size_t)r0 * ldc + c0]) =
                make_float2(acc[mi][ni][0], acc[mi][ni][1]);
            *reinterpret_cast<float2*>(&Cbase[(size_t)(r0 + 8) * ldc + c0]) =
                make_float2(acc[mi][ni][2], acc[mi][ni][3]);
        }
}

__global__ void qkv_kernel(const float* __restrict__ x,
                           const float* __restrict__ wq,
                           const float* __restrict__ wk,
                           const float* __restrict__ wv) {
    int n0 = blockIdx.x * 128;
    int sp = blockIdx.y;
    const float* W;
    if (n0 < HD)            W = wq + (size_t)n0 * DIMq;
    else if (n0 < HD + KVD) W = wk + (size_t)(n0 - HD) * DIMq;
    else                    W = wv + (size_t)(n0 - HD - KVD) * DIMq;
    gemm_tile_mma(x, W, g_qkvp[sp] + n0, NTOT, sp * (GK / SPLITK), GK / BKg / SPLITK);
}

__global__ void out_kernel(const float* __restrict__ wo) {
    int n0 = blockIdx.x * 128;
    int sp = blockIdx.y;
    gemm_tile_mma(g_y, wo + (size_t)n0 * DIMq, g_outp[sp] + n0, DIMq,
                  sp * (GK / SPLITKO), GK / BKg / SPLITKO);
}

__global__ void reduce_out_kernel(float* __restrict__ out) {
    int i = blockIdx.x * 256 + threadIdx.x;
    if (i >= M64 * DIMq / 4) return;
    float4 r = reinterpret_cast<const float4*>(g_outp[0])[i];
#pragma unroll
    for (int sp = 1; sp < SPLITKO; sp++) {
        float4 v = reinterpret_cast<const float4*>(g_outp[sp])[i];
        r.x += v.x; r.y += v.y; r.z += v.z; r.w += v.w;
    }
    reinterpret_cast<float4*>(out)[i] = r;
}

// ---------------- fused split-K reduce + RoPE (two kernels) ------------------
#define QPAIRS (M64*Hq*(Dq/2))   // 131072
#define KPAIRS (M64*KVq*(Dq/2))  // 32768
#define VQUADS (M64*KVD/4)       // 16384
__global__ void rope_q_kernel(const float* __restrict__ fc,
                              const float* __restrict__ fs) {
    int idx = blockIdx.x * blockDim.x + threadIdx.x;
    if (idx >= QPAIRS) return;
    int i = idx & 63;
    int h = (idx >> 6) & (Hq - 1);
    int m = idx >> 11;
    int t = m & (Tq - 1), b = m >> 4;
    size_t off = (size_t)m * NTOT + h * Dq + 2 * i;
    float x0 = 0.f, x1 = 0.f;
#pragma unroll
    for (int sp = 0; sp < SPLITK; sp++) {
        float2 p = *reinterpret_cast<const float2*>(&g_qkvp[sp][off]);
        x0 += p.x; x1 += p.y;
    }
    float c = fc[t * 64 + i], s = fs[t * 64 + i];
    int kv = h >> 2, hl = h & 3;
    float* q = g_qatt + ((((size_t)b * KVq + kv) * AROWS) + hl * Tq + t) * Dq + 2 * i;
    q[0] = (x0 * c - x1 * s) * SCALE_F;
    q[1] = (x0 * s + x1 * c) * SCALE_F;
}

__global__ void rope_kv_kernel(const float* __restrict__ fc,
                               const float* __restrict__ fs) {
    int idx = blockIdx.x * blockDim.x + threadIdx.x;
    if (idx < KPAIRS) {
        int i = idx & 63;
        int kv = (idx >> 6) & (KVq - 1);
        int m = idx >> 9;
        int t = m & (Tq - 1);
        size_t off = (size_t)m * NTOT + HD + kv * Dq + 2 * i;
        float x0 = 0.f, x1 = 0.f;
#pragma unroll
        for (int sp = 0; sp < SPLITK; sp++) {
            float2 p = *reinterpret_cast<const float2*>(&g_qkvp[sp][off]);
            x0 += p.x; x1 += p.y;
        }
        float c = fc[t * 64 + i], s = fs[t * 64 + i];
        float* k = g_knew + ((size_t)m * KVq + kv) * Dq + 2 * i;
        k[0] = x0 * c - x1 * s;
        k[1] = x0 * s + x1 * c;
    } else if (idx < KPAIRS + VQUADS) {
        int j = idx - KPAIRS;
        int m = j >> 8;
        int c4 = (j & 255) * 4;
        size_t off = (size_t)m * NTOT + HD + KVD + c4;
        float4 r = make_float4(0.f, 0.f, 0.f, 0.f);
#pragma unroll
        for (int sp = 0; sp < SPLITK; sp++) {
            float4 v = *reinterpret_cast<const float4*>(&g_qkvp[sp][off]);
            r.x += v.x; r.y += v.y; r.z += v.z; r.w += v.w;
        }
        *reinterpret_cast<float4*>(&g_vnew[(size_t)m * KVD + c4]) = r;
    }
}

// ================= tensor-core flash attention v8 ===========================
// R12 fragment path + DOUBLE-BUFFERED packed smem: sts(t) overlaps compute(t-1),
// ONE barrier per tile. 128 threads / 4 warps, warp owns 16 q-rows x 32 keys.
#define KV_TILE 32
#define KROWW 72                          // packed K row stride (words)
#define VROWW 136                         // packed V pair-row stride (words)
#define KBUFW (32 * KROWW)                // 2304 words per K buffer
#define VBUFW (16 * VROWW)                // 2176 words per V buffer

__global__ void __launch_bounds__(128, 2)
attn_kernel(const float* __restrict__ k_cache,
            const float* __restrict__ v_cache,
            const int* __restrict__ input_pos) {
    __shared__ unsigned smemA[2 * KBUFW + 2 * VBUFW];
    __shared__ int pos_s[Tq];

    const int tid  = threadIdx.x;
    const int lane = tid & 31;
    const int gid  = lane >> 2;
    const int ctg  = lane & 3;
    const int wid  = tid >> 5;
    const int r0   = wid * 16 + gid;

    const int bk = blockIdx.x & 31;
    const int split = blockIdx.x >> 5;
    const int b = bk >> 3, kv = bk & 7;

    if (tid < Tq) pos_s[tid] = input_pos[tid];

    const int start_pos = __ldg(&input_pos[0]);
    const int limit = __ldg(&input_pos[Tq - 1]) + 1;
    const int totalTiles = (limit + KV_TILE - 1) / KV_TILE;
    const int tbase = totalTiles / NSPLIT, trem = totalTiles % NSPLIT;
    const int t0 = split * tbase + min(split, trem);
    const int tcount = tbase + (split < trem);
    const int sbeg = t0 * KV_TILE;
    const int send = min((t0 + tcount) * KV_TILE, limit);

    // ---- Q into fp16 registers: 8 k16-chunks x 4 regs ----
    unsigned qreg[8][4];
    {
        const float* qa = g_qatt + (((size_t)b * KVq + kv) * AROWS + r0) * Dq;
        const float* qb = qa + 8 * Dq;
#pragma unroll
        for (int ks = 0; ks < 8; ks++) {
            int c0 = ks * 16 + 2 * ctg;
            qreg[ks][0] = h2pack(qa[c0],     qa[c0 + 1]);
            qreg[ks][1] = h2pack(qb[c0],     qb[c0 + 1]);
            qreg[ks][2] = h2pack(qa[c0 + 8], qa[c0 + 9]);
            qreg[ks][3] = h2pack(qb[c0 + 8], qb[c0 + 9]);
        }
    }

    const unsigned sbK = smem_u32(smemA);                 // K buffers
    const unsigned sbV = sbK + 2u * KBUFW * 4u;           // V buffers

    // fill mappings
    const int kr  = tid >> 2;            // K row 0..31
    const int kq  = tid & 3;             // covers d [kq*32, kq*32+32)
    const int vp  = tid >> 3;            // V pair-row 0..15 (keys 2vp, 2vp+1)
    const int vdb = (tid & 7) * 16;      // V d base

    float4 kpre[8], vpre[8];

    auto row_ptr_k = [&](int s) -> const float* {
        if (s >= start_pos && s < start_pos + Tq)
            return &g_knew[((size_t)(b * Tq + (s - start_pos)) * KVq + kv) * Dq];
        return &k_cache[(((size_t)b * Sq + s) * KVq + kv) * Dq];
    };
    auto row_ptr_v = [&](int s) -> const float* {
        if (s >= start_pos && s < start_pos + Tq)
            return &g_vnew[(size_t)(b * Tq + (s - start_pos)) * KVD + kv * Dq];
        return &v_cache[(((size_t)b * Sq + s) * KVq + kv) * Dq];
    };

    auto ldg_tile = [&](int s0t) {
        const float* kp = row_ptr_k(s0t + kr) + kq * 32;
#pragma unroll
        for (int j = 0; j < 8; j++)
            kpre[j] = *reinterpret_cast<const float4*>(kp + j * 4);
        const float* v0 = row_ptr_v(s0t + 2 * vp)     + vdb;
        const float* v1 = row_ptr_v(s0t + 2 * vp + 1) + vdb;
#pragma unroll
        for (int j = 0; j < 4; j++) {
            vpre[j]     = *reinterpret_cast<const float4*>(v0 + j * 4);
            vpre[j + 4] = *reinterpret_cast<const float4*>(v1 + j * 4);
        }
    };

    auto sts_tile = [&](int buf) {
        // K: two k16 chunks (ks=2kq, 2kq+1); chunk layout [w0 w4][w1 w5][w2 w6][w3 w7]
        unsigned kb = sbK + (unsigned)(buf * KBUFW) * 4u;
#pragma unroll
        for (int ks = 0; ks < 2; ks++) {
            unsigned cb = kb + (unsigned)(kr * KROWW) * 4u + (2 * kq + ks) * 32u;
#pragma unroll
            for (int c = 0; c < 8; c++) {
                float4 f = kpre[ks * 4 + (c >> 1)];
                float lo = (c & 1) ? f.z : f.x;
                float hi = (c & 1) ? f.w : f.y;
                sts32(cb + (unsigned)((c & 3) * 8 + (c >> 2) * 4), h2pack(lo, hi));
            }
        }
        // V: pair-row vp, d = vdb..vdb+15: word = half2(V[2vp][d], V[2vp+1][d])
        unsigned vb = sbV + (unsigned)(buf * VBUFW + vp * VROWW + vdb) * 4u;
#pragma unroll
        for (int j = 0; j < 4; j++) {
            float4 a = vpre[j], c = vpre[j + 4];
            sts32(vb + (unsigned)(j * 4 + 0) * 4u, h2pack(a.x, c.x));
            sts32(vb + (unsigned)(j * 4 + 1) * 4u, h2pack(a.y, c.y));
            sts32(vb + (unsigned)(j * 4 + 2) * 4u, h2pack(a.z, c.z));
            sts32(vb + (unsigned)(j * 4 + 3) * 4u, h2pack(a.w, c.w));
        }
    };

    if (tcount > 0) ldg_tile(sbeg);

    float acc[16][4];
#pragma unroll
    for (int nt = 0; nt < 16; nt++)
#pragma unroll
        for (int j = 0; j < 4; j++) acc[nt][j] = 0.f;
    float m0 = -FLT_MAX, m1 = -FLT_MAX, l0 = 0.f, l1 = 0.f;

    for (int t = 0; t < tcount; t++) {
        const int s0 = sbeg + t * KV_TILE;
        const int buf = t & 1;
        // publish tile t into buf; last reader of this buf (compute t-2) is
        // behind the barrier of iteration t-1 -> safe with ONE barrier/tile.
        sts_tile(buf);
        __syncthreads();
        if (t + 1 < tcount) ldg_tile(s0 + KV_TILE);

        const unsigned kb = sbK + (unsigned)(buf * KBUFW) * 4u;
        const unsigned vb = sbV + (unsigned)(buf * VBUFW) * 4u;

        // ---- QK^T: 16 rows x 32 keys, fp16 k16 steps ----
        float sc[4][4];
#pragma unroll
        for (int nt = 0; nt < 4; nt++)
#pragma unroll
            for (int j = 0; j < 4; j++) sc[nt][j] = 0.f;
#pragma unroll
        for (int ks = 0; ks < 8; ks++) {
#pragma unroll
            for (int nt = 0; nt < 4; nt++) {
                int key = nt * 8 + gid;
                unsigned bfr[2];
                lds64(bfr[0], bfr[1],
                      kb + (unsigned)(key * KROWW) * 4u + (unsigned)(ks * 32 + ctg * 8));
                mma_f16(sc[nt], qreg[ks], bfr);
            }
        }

        // ---- mask + warp-local online softmax ----
        const int p0 = pos_s[gid];
        const int p1 = pos_s[gid + 8];
        float tm0 = -FLT_MAX, tm1 = -FLT_MAX;
#pragma unroll
        for (int nt = 0; nt < 4; nt++) {
            int cb = nt * 8 + 2 * ctg;
            int sA = s0 + cb, sB = sA + 1;
            sc[nt][0] = (sA < send && sA <= p0) ? sc[nt][0] : -FLT_MAX;
            sc[nt][1] = (sB < send && sB <= p0) ? sc[nt][1] : -FLT_MAX;
            sc[nt][2] = (sA < send && sA <= p1) ? sc[nt][2] : -FLT_MAX;
            sc[nt][3] = (sB < send && sB <= p1) ? sc[nt][3] : -FLT_MAX;
            tm0 = fmaxf(tm0, fmaxf(sc[nt][0], sc[nt][1]));
            tm1 = fmaxf(tm1, fmaxf(sc[nt][2], sc[nt][3]));
        }
        tm0 = fmaxf(tm0, __shfl_xor_sync(0xFFFFFFFF, tm0, 1));
        tm0 = fmaxf(tm0, __shfl_xor_sync(0xFFFFFFFF, tm0, 2));
        tm1 = fmaxf(tm1, __shfl_xor_sync(0xFFFFFFFF, tm1, 1));
        tm1 = fmaxf(tm1, __shfl_xor_sync(0xFFFFFFFF, tm1, 2));
        float mn0 = fmaxf(m0, tm0), mn1 = fmaxf(m1, tm1);
        float scl0 = __expf(m0 - mn0), scl1 = __expf(m1 - mn1);

        unsigned ps[4][2];
        float su0 = 0.f, su1 = 0.f;
#pragma unroll
        for (int nt = 0; nt < 4; nt++) {
            float e0 = __expf(sc[nt][0] - mn0), e1 = __expf(sc[nt][1] - mn0);
            float e2 = __expf(sc[nt][2] - mn1), e3 = __expf(sc[nt][3] - mn1);
            ps[nt][0] = h2pack(e0, e1);
            ps[nt][1] = h2pack(e2, e3);
            float2 f0 = __half22float2(*reinterpret_cast<__half2*>(&ps[nt][0]));
            float2 f1 = __half22float2(*reinterpret_cast<__half2*>(&ps[nt][1]));
            su0 += f0.x + f0.y;
            su1 += f1.x + f1.y;
        }
        su0 += __shfl_xor_sync(0xFFFFFFFF, su0, 1);
        su0 += __shfl_xor_sync(0xFFFFFFFF, su0, 2);
        su1 += __shfl_xor_sync(0xFFFFFFFF, su1, 1);
        su1 += __shfl_xor_sync(0xFFFFFFFF, su1, 2);
        l0 = l0 * scl0 + su0;
        l1 = l1 * scl1 + su1;
        m0 = mn0; m1 = mn1;

        // ---- rescale ----
#pragma unroll
        for (int nt = 0; nt < 16; nt++) {
            acc[nt][0] *= scl0; acc[nt][1] *= scl0;
            acc[nt][2] *= scl1; acc[nt][3] *= scl1;
        }

        // ---- P@V: C-frag == A-frag (no shfl), V fragments via LDS.32 ----
#pragma unroll
        for (int kt = 0; kt < 2; kt++) {
            unsigned a[4];
            a[0] = ps[2 * kt][0];
            a[1] = ps[2 * kt][1];
            a[2] = ps[2 * kt + 1][0];
            a[3] = ps[2 * kt + 1][1];
#pragma unroll
            for (int nt = 0; nt < 16; nt++) {
                int n = nt * 8 + gid;
                unsigned bfr[2];
                bfr[0] = lds32(vb + (unsigned)((8 * kt + ctg) * VROWW + n) * 4u);
                bfr[1] = lds32(vb + (unsigned)((8 * kt + ctg + 4) * VROWW + n) * 4u);
                mma_f16(acc[nt], a, bfr);
            }
        }
    }

    // ---- write split partials ----
    {
        float* pbase = g_pacc + ((size_t)split * Bq * KVq + bk) * AROWS * Dq;
#pragma unroll
        for (int nt = 0; nt < 16; nt++) {
            int col = nt * 8 + 2 * ctg;
            *reinterpret_cast<float2*>(&pbase[(size_t)r0 * Dq + col]) =
                make_float2(acc[nt][0], acc[nt][1]);
            *reinterpret_cast<float2*>(&pbase[(size_t)(r0 + 8) * Dq + col]) =
                make_float2(acc[nt][2], acc[nt][3]);
        }
    }
    if (ctg == 0) {
        int o = (split * Bq * KVq + bk) * AROWS;
        g_pm[o + r0] = m0;      g_pl[o + r0] = l0;
        g_pm[o + r0 + 8] = m1;  g_pl[o + r0 + 8] = l1;
    }
}

// ---------------- combine splits --------------------------------------------
__global__ void combine_kernel() {
    int idx = blockIdx.x * 256 + threadIdx.x;
    if (idx >= Bq * KVq * AROWS * Dq) return;
    int d = idx & 127;
    int r = (idx >> 7) & 63;
    int bk = idx >> 13;
    float M = -FLT_MAX;
#pragma unroll
    for (int sp = 0; sp < NSPLIT; sp++)
        M = fmaxf(M, g_pm[(sp * Bq * KVq + bk) * AROWS + r]);
    float L = 0.f, Y = 0.f;
#pragma unroll
    for (int sp = 0; sp < NSPLIT; sp++) {
        int o = (sp * Bq * KVq + bk) * AROWS + r;
        float w = __expf(g_pm[o] - M);
        L += g_pl[o] * w;
        Y += g_pacc[(size_t)o * Dq + d] * w;
    }
    float y = Y / L;
    int b = bk >> 3, kv = bk & 7;
    int hl = r >> 4, t = r & 15;
    int h = kv * GQ + hl;
    int m = b * Tq + t;
    g_y[(size_t)m * HD + h * Dq + d] = y;
}

// ---------------- launch -----------------------------------------------------
extern "C" void kernel_launch(void* const* d_in, const int* in_sizes, int n_in,
                              void* d_out, int out_size) {
    const float* x  = (const float*)d_in[0];
    const float* fc = (const float*)d_in[1];
    const float* fs = (const float*)d_in[2];
    const int*  pos = (const int*)  d_in[3];
    const float* kc = (const float*)d_in[5];
    const float* vc = (const float*)d_in[6];
    const float* wq = (const float*)d_in[7];
    const float* wk = (const float*)d_in[8];
    const float* wv = (const float*)d_in[9];
    const float* wo = (const float*)d_in[10];
    float* out = (float*)d_out;

    cudaFuncSetAttribute(qkv_kernel, cudaFuncAttributeMaxDynamicSharedMemorySize,
                         GEMM_SMEM_BYTES);
    cudaFuncSetAttribute(out_kernel, cudaFuncAttributeMaxDynamicSharedMemorySize,
                         GEMM_SMEM_BYTES);

    qkv_kernel<<<dim3(NTOT / 128, SPLITK), 256, GEMM_SMEM_BYTES>>>(x, wq, wk, wv);
    rope_q_kernel<<<(QPAIRS + 255) / 256, 256>>>(fc, fs);
    rope_kv_kernel<<<(KPAIRS + VQUADS + 255) / 256, 256>>>(fc, fs);
    attn_kernel<<<NSPLIT * Bq * KVq, 128>>>(kc, vc, pos);   // 4th launch -> ncu
    combine_kernel<<<(Bq * KVq * AROWS * Dq + 255) / 256, 256>>>();
    out_kernel<<<dim3(DIMq / 128, SPLITKO), 256, GEMM_SMEM_BYTES>>>(wo);
    reduce_out_kernel<<<(M64 * DIMq / 4 + 255) / 256, 256>>>(out);
}

// round 15
// speedup vs baseline: 1.1473x; 1.0325x over previous
#include <cuda_runtime.h>
#include <cuda_bf16.h>
#include <cuda_fp16.h>
#include <math.h>
#include <float.h>

// Problem constants
#define Bq   4
#define Tq   16
#define Sq   4096
#define Hq   32
#define KVq  8
#define Dq   128
#define DIMq 4096
#define HD   (Hq*Dq)          // 4096
#define KVD  (KVq*Dq)         // 1024
#define NTOT (HD + 2*KVD)     // 6144
#define M64  (Bq*Tq)          // 64
#define GQ   (Hq/KVq)         // 4
#define AROWS 64
#define NSPLIT 9
#define SCALE_F 0.08838834764831843f
#define SPLITK  8             // qkv
#define SPLITKO 8             // out proj

// ---------------- scratch ----------------------------------------------------
__device__ float g_qkvp[SPLITK][M64 * NTOT];
__device__ float g_outp[SPLITKO][M64 * DIMq];
__device__ float g_qatt[Bq*KVq*AROWS*Dq];
__device__ float g_knew[M64*KVq*Dq];
__device__ float g_vnew[M64*KVD];
__device__ float g_pacc[(size_t)NSPLIT*Bq*KVq*AROWS*Dq];
__device__ float g_pm  [NSPLIT*Bq*KVq*AROWS];
__device__ float g_pl  [NSPLIT*Bq*KVq*AROWS];
__device__ float g_y   [M64 * HD];

// ================= shared helpers ===========================================
__device__ __forceinline__ unsigned smem_u32(const void* p) {
    unsigned a;
    asm("{ .reg .u64 t; cvta.to.shared.u64 t, %1; cvt.u32.u64 %0, t; }"
        : "=r"(a) : "l"(p));
    return a;
}
__device__ __forceinline__ unsigned f2tf32(float x) {
    unsigned u; asm("cvt.rna.tf32.f32 %0, %1;" : "=r"(u) : "f"(x)); return u;
}
__device__ __forceinline__ unsigned h2pack(float lo, float hi) {
    unsigned r; asm("cvt.rn.f16x2.f32 %0, %1, %2;" : "=r"(r) : "f"(hi), "f"(lo));
    return r;
}
__device__ __forceinline__ void mma_tf32(float c[4], const unsigned a[4], const unsigned b[2]) {
    asm volatile(
        "mma.sync.aligned.m16n8k8.row.col.f32.tf32.tf32.f32 "
        "{%0,%1,%2,%3}, {%4,%5,%6,%7}, {%8,%9}, {%0,%1,%2,%3};\n"
        : "+f"(c[0]), "+f"(c[1]), "+f"(c[2]), "+f"(c[3])
        : "r"(a[0]), "r"(a[1]), "r"(a[2]), "r"(a[3]), "r"(b[0]), "r"(b[1]));
}
__device__ __forceinline__ void mma_f16(float c[4], const unsigned a[4], const unsigned b[2]) {
    asm volatile(
        "mma.sync.aligned.m16n8k16.row.col.f32.f16.f16.f32 "
        "{%0,%1,%2,%3}, {%4,%5,%6,%7}, {%8,%9}, {%0,%1,%2,%3};\n"
        : "+f"(c[0]), "+f"(c[1]), "+f"(c[2]), "+f"(c[3])
        : "r"(a[0]), "r"(a[1]), "r"(a[2]), "r"(a[3]), "r"(b[0]), "r"(b[1]));
}
__device__ __forceinline__ void cpasync16(unsigned saddr, const void* g) {
    asm volatile("cp.async.ca.shared.global [%0], [%1], 16;" :: "r"(saddr), "l"(g));
}
__device__ __forceinline__ void sts32(unsigned baddr, unsigned v) {
    asm volatile("st.shared.u32 [%0], %1;" :: "r"(baddr), "r"(v));
}
__device__ __forceinline__ unsigned lds32(unsigned baddr) {
    unsigned x; asm volatile("ld.shared.u32 %0, [%1];" : "=r"(x) : "r"(baddr));
    return x;
}
__device__ __forceinline__ void lds64(unsigned &x, unsigned &y, unsigned baddr) {
    asm volatile("ld.shared.v2.u32 {%0, %1}, [%2];" : "=r"(x), "=r"(y) : "r"(baddr));
}

// ================= tf32 split-K GEMM, 64x128 block tile, 3-stage ============
#define BKg      32
#define GSTAGES  3
#define GSTRIDE  36
#define GSTG_FLT (192 * GSTRIDE)
#define GEMM_SMEM_BYTES (GSTAGES * GSTG_FLT * 4)   // 82944
#define GK       4096

__device__ __forceinline__ void gemm_tile_mma(const float* __restrict__ A,
                                              const float* __restrict__ W,
                                              float* __restrict__ Cbase,
                                              int ldc, int kbeg, int nks) {
    extern __shared__ float smf[];
    const int tid  = threadIdx.x;
    const int lane = tid & 31;
    const int wid  = tid >> 5;
    const int gid  = lane >> 2;
    const int ctg  = lane & 3;
    const int wm   = wid & 1;
    const int wn   = wid >> 1;
    const int frA  = tid >> 2;
    const int fkA  = (tid & 3) * 8;
    const int frW  = tid >> 1;
    const int fkW  = (tid & 1) * 16;
    const unsigned sbase = smem_u32(smf);

    float acc[2][4][4];
#pragma unroll
    for (int mi = 0; mi < 2; mi++)
#pragma unroll
        for (int ni = 0; ni < 4; ni++)
#pragma unroll
            for (int j = 0; j < 4; j++) acc[mi][ni][j] = 0.f;

#pragma unroll
    for (int s = 0; s < GSTAGES - 1; s++) {
        unsigned sa = sbase + (unsigned)(s * GSTG_FLT + frA * GSTRIDE + fkA) * 4u;
        unsigned sw = sbase + (unsigned)(s * GSTG_FLT + (64 + frW) * GSTRIDE + fkW) * 4u;
        const float* ga = A + (size_t)frA * GK + kbeg + s * BKg + fkA;
        const float* gw = W + (size_t)frW * GK + kbeg + s * BKg + fkW;
        cpasync16(sa, ga);       cpasync16(sa + 16, ga + 4);
        cpasync16(sw, gw);       cpasync16(sw + 16, gw + 4);
        cpasync16(sw + 32, gw + 8); cpasync16(sw + 48, gw + 12);
        asm volatile("cp.async.commit_group;");
    }

    for (int i = 0; i < nks; i++) {
        asm volatile("cp.async.wait_group 1;");
        __syncthreads();
        int bufi = i % 3;
        const float* As = smf + bufi * GSTG_FLT;
        const float* Ws = As + 64 * GSTRIDE;

#pragma unroll
        for (int ks = 0; ks < 4; ks++) {
            const int k = ks * 8;
            unsigned af[2][4], bf[4][2];
#pragma unroll
            for (int mi = 0; mi < 2; mi++) {
                int r = wm * 32 + mi * 16 + gid;
                af[mi][0] = f2tf32(As[r * GSTRIDE + k + ctg]);
                af[mi][1] = f2tf32(As[(r + 8) * GSTRIDE + k + ctg]);
                af[mi][2] = f2tf32(As[r * GSTRIDE + k + ctg + 4]);
                af[mi][3] = f2tf32(As[(r + 8) * GSTRIDE + k + ctg + 4]);
            }
#pragma unroll
            for (int ni = 0; ni < 4; ni++) {
                int n = wn * 32 + ni * 8 + gid;
                bf[ni][0] = f2tf32(Ws[n * GSTRIDE + k + ctg]);
                bf[ni][1] = f2tf32(Ws[n * GSTRIDE + k + ctg + 4]);
            }
#pragma unroll
            for (int mi = 0; mi < 2; mi++)
#pragma unroll
                for (int ni = 0; ni < 4; ni++)
                    mma_tf32(acc[mi][ni], af[mi], bf[ni]);
        }

        if (i + GSTAGES - 1 < nks) {
            int s = (i + 2) % 3;
            int k0 = kbeg + (i + 2) * BKg;
            unsigned sa = sbase + (unsigned)(s * GSTG_FLT + frA * GSTRIDE + fkA) * 4u;
            unsigned sw = sbase + (unsigned)(s * GSTG_FLT + (64 + frW) * GSTRIDE + fkW) * 4u;
            const float* ga = A + (size_t)frA * GK + k0 + fkA;
            const float* gw = W + (size_t)frW * GK + k0 + fkW;
            cpasync16(sa, ga);       cpasync16(sa + 16, ga + 4);
            cpasync16(sw, gw);       cpasync16(sw + 16, gw + 4);
            cpasync16(sw + 32, gw + 8); cpasync16(sw + 48, gw + 12);
            asm volatile("cp.async.commit_group;");
        } else {
            asm volatile("cp.async.commit_group;");
        }
    }

#pragma unroll
    for (int mi = 0; mi < 2; mi++)
#pragma unroll
        for (int ni = 0; ni < 4; ni++) {
            int r0 = wm * 32 + mi * 16 + gid;
            int c0 = wn * 32 + ni * 8 + 2 * ctg;
            *reinterpret_cast<float2*>(&Cbase[(size_t)r0 * ldc + c0]) =
                make_float2(acc[mi][ni][0], acc[mi][ni][1]);
            *reinterpret_cast<float2*>(&Cbase[(size_t)(r0 + 8) * ldc + c0]) =
                make_float2(acc[mi][ni][2], acc[mi][ni][3]);
        }
}

__global__ void qkv_kernel(const float* __restrict__ x,
                           const float* __restrict__ wq,
                           const float* __restrict__ wk,
                           const float* __restrict__ wv) {
    int n0 = blockIdx.x * 128;
    int sp = blockIdx.y;
    const float* W;
    if (n0 < HD)            W = wq + (size_t)n0 * DIMq;
    else if (n0 < HD + KVD) W = wk + (size_t)(n0 - HD) * DIMq;
    else                    W = wv + (size_t)(n0 - HD - KVD) * DIMq;
    gemm_tile_mma(x, W, g_qkvp[sp] + n0, NTOT, sp * (GK / SPLITK), GK / BKg / SPLITK);
}

__global__ void out_kernel(const float* __restrict__ wo) {
    int n0 = blockIdx.x * 128;
    int sp = blockIdx.y;
    gemm_tile_mma(g_y, wo + (size_t)n0 * DIMq, g_outp[sp] + n0, DIMq,
                  sp * (GK / SPLITKO), GK / BKg / SPLITKO);
}

__global__ void reduce_out_kernel(float* __restrict__ out) {
    int i = blockIdx.x * 256 + threadIdx.x;
    if (i >= M64 * DIMq / 4) return;
    float4 r = reinterpret_cast<const float4*>(g_outp[0])[i];
#pragma unroll
    for (int sp = 1; sp < SPLITKO; sp++) {
        float4 v = reinterpret_cast<const float4*>(g_outp[sp])[i];
        r.x += v.x; r.y += v.y; r.z += v.z; r.w += v.w;
    }
    reinterpret_cast<float4*>(out)[i] = r;
}

// ---------------- fused split-K reduce + RoPE (single kernel) ----------------
#define QPAIRS (M64*Hq*(Dq/2))   // 131072
#define KPAIRS (M64*KVq*(Dq/2))  // 32768
#define VQUADS (M64*KVD/4)       // 16384
__global__ void rope_all_kernel(const float* __restrict__ fc,
                                const float* __restrict__ fs) {
    int idx = blockIdx.x * blockDim.x + threadIdx.x;
    if (idx < QPAIRS) {
        int i = idx & 63;
        int h = (idx >> 6) & (Hq - 1);
        int m = idx >> 11;
        int t = m & (Tq - 1), b = m >> 4;
        size_t off = (size_t)m * NTOT + h * Dq + 2 * i;
        float x0 = 0.f, x1 = 0.f;
#pragma unroll
        for (int sp = 0; sp < SPLITK; sp++) {
            float2 p = *reinterpret_cast<const float2*>(&g_qkvp[sp][off]);
            x0 += p.x; x1 += p.y;
        }
        float c = fc[t * 64 + i], s = fs[t * 64 + i];
        int kv = h >> 2, hl = h & 3;
        float* q = g_qatt + ((((size_t)b * KVq + kv) * AROWS) + hl * Tq + t) * Dq + 2 * i;
        q[0] = (x0 * c - x1 * s) * SCALE_F;
        q[1] = (x0 * s + x1 * c) * SCALE_F;
    } else if (idx < QPAIRS + KPAIRS) {
        int j = idx - QPAIRS;
        int i = j & 63;
        int kv = (j >> 6) & (KVq - 1);
        int m = j >> 9;
        int t = m & (Tq - 1);
        size_t off = (size_t)m * NTOT + HD + kv * Dq + 2 * i;
        float x0 = 0.f, x1 = 0.f;
#pragma unroll
        for (int sp = 0; sp < SPLITK; sp++) {
            float2 p = *reinterpret_cast<const float2*>(&g_qkvp[sp][off]);
            x0 += p.x; x1 += p.y;
        }
        float c = fc[t * 64 + i], s = fs[t * 64 + i];
        float* k = g_knew + ((size_t)m * KVq + kv) * Dq + 2 * i;
        k[0] = x0 * c - x1 * s;
        k[1] = x0 * s + x1 * c;
    } else if (idx < QPAIRS + KPAIRS + VQUADS) {
        int j = idx - (QPAIRS + KPAIRS);
        int m = j >> 8;
        int c4 = (j & 255) * 4;
        size_t off = (size_t)m * NTOT + HD + KVD + c4;
        float4 r = make_float4(0.f, 0.f, 0.f, 0.f);
#pragma unroll
        for (int sp = 0; sp < SPLITK; sp++) {
            float4 v = *reinterpret_cast<const float4*>(&g_qkvp[sp][off]);
            r.x += v.x; r.y += v.y; r.z += v.z; r.w += v.w;
        }
        *reinterpret_cast<float4*>(&g_vnew[(size_t)m * KVD + c4]) = r;
    }
}

// ================= tensor-core flash attention (R14 + vectorized Q fill) ====
#define KV_TILE 32
#define KROWW 72                          // packed K row stride (words)
#define VROWW 136                         // packed V pair-row stride (words)
#define KBUFW (32 * KROWW)                // 2304 words per K buffer
#define VBUFW (16 * VROWW)                // 2176 words per V buffer

__global__ void __launch_bounds__(128, 2)
attn_kernel(const float* __restrict__ k_cache,
            const float* __restrict__ v_cache,
            const int* __restrict__ input_pos) {
    __shared__ unsigned smemA[2 * KBUFW + 2 * VBUFW];
    __shared__ int pos_s[Tq];

    const int tid  = threadIdx.x;
    const int lane = tid & 31;
    const int gid  = lane >> 2;
    const int ctg  = lane & 3;
    const int wid  = tid >> 5;
    const int r0   = wid * 16 + gid;

    const int bk = blockIdx.x & 31;
    const int split = blockIdx.x >> 5;
    const int b = bk >> 3, kv = bk & 7;

    if (tid < Tq) pos_s[tid] = input_pos[tid];

    const int start_pos = __ldg(&input_pos[0]);
    const int limit = __ldg(&input_pos[Tq - 1]) + 1;
    const int totalTiles = (limit + KV_TILE - 1) / KV_TILE;
    const int tbase = totalTiles / NSPLIT, trem = totalTiles % NSPLIT;
    const int t0 = split * tbase + min(split, trem);
    const int tcount = tbase + (split < trem);
    const int sbeg = t0 * KV_TILE;
    const int send = min((t0 + tcount) * KV_TILE, limit);

    // ---- Q into fp16 registers: 8 k16-chunks x 4 regs (float2 loads) ----
    unsigned qreg[8][4];
    {
        const float* qa = g_qatt + (((size_t)b * KVq + kv) * AROWS + r0) * Dq;
        const float* qb = qa + 8 * Dq;
#pragma unroll
        for (int ks = 0; ks < 8; ks++) {
            int c0 = ks * 16 + 2 * ctg;
            float2 a1 = *reinterpret_cast<const float2*>(qa + c0);
            float2 b1 = *reinterpret_cast<const float2*>(qb + c0);
            float2 a2 = *reinterpret_cast<const float2*>(qa + c0 + 8);
            float2 b2 = *reinterpret_cast<const float2*>(qb + c0 + 8);
            qreg[ks][0] = h2pack(a1.x, a1.y);
            qreg[ks][1] = h2pack(b1.x, b1.y);
            qreg[ks][2] = h2pack(a2.x, a2.y);
            qreg[ks][3] = h2pack(b2.x, b2.y);
        }
    }

    const unsigned sbK = smem_u32(smemA);                 // K buffers
    const unsigned sbV = sbK + 2u * KBUFW * 4u;           // V buffers

    // fill mappings
    const int kr  = tid >> 2;            // K row 0..31
    const int kq  = tid & 3;             // covers d [kq*32, kq*32+32)
    const int vp  = tid >> 3;            // V pair-row 0..15 (keys 2vp, 2vp+1)
    const int vdb = (tid & 7) * 16;      // V d base

    float4 kpre[8], vpre[8];

    auto row_ptr_k = [&](int s) -> const float* {
        if (s >= start_pos && s < start_pos + Tq)
            return &g_knew[((size_t)(b * Tq + (s - start_pos)) * KVq + kv) * Dq];
        return &k_cache[(((size_t)b * Sq + s) * KVq + kv) * Dq];
    };
    auto row_ptr_v = [&](int s) -> const float* {
        if (s >= start_pos && s < start_pos + Tq)
            return &g_vnew[(size_t)(b * Tq + (s - start_pos)) * KVD + kv * Dq];
        return &v_cache[(((size_t)b * Sq + s) * KVq + kv) * Dq];
    };

    auto ldg_tile = [&](int s0t) {
        const float* kp = row_ptr_k(s0t + kr) + kq * 32;
#pragma unroll
        for (int j = 0; j < 8; j++)
            kpre[j] = *reinterpret_cast<const float4*>(kp + j * 4);
        const float* v0 = row_ptr_v(s0t + 2 * vp)     + vdb;
        const float* v1 = row_ptr_v(s0t + 2 * vp + 1) + vdb;
#pragma unroll
        for (int j = 0; j < 4; j++) {
            vpre[j]     = *reinterpret_cast<const float4*>(v0 + j * 4);
            vpre[j + 4] = *reinterpret_cast<const float4*>(v1 + j * 4);
        }
    };

    auto sts_tile = [&](int buf) {
        unsigned kb = sbK + (unsigned)(buf * KBUFW) * 4u;
#pragma unroll
        for (int ks = 0; ks < 2; ks++) {
            unsigned cb = kb + (unsigned)(kr * KROWW) * 4u + (2 * kq + ks) * 32u;
#pragma unroll
            for (int c = 0; c < 8; c++) {
                float4 f = kpre[ks * 4 + (c >> 1)];
                float lo = (c & 1) ? f.z : f.x;
                float hi = (c & 1) ? f.w : f.y;
                sts32(cb + (unsigned)((c & 3) * 8 + (c >> 2) * 4), h2pack(lo, hi));
            }
        }
        unsigned vb = sbV + (unsigned)(buf * VBUFW + vp * VROWW + vdb) * 4u;
#pragma unroll
        for (int j = 0; j < 4; j++) {
            float4 a = vpre[j], c = vpre[j + 4];
            sts32(vb + (unsigned)(j * 4 + 0) * 4u, h2pack(a.x, c.x));
            sts32(vb + (unsigned)(j * 4 + 1) * 4u, h2pack(a.y, c.y));
            sts32(vb + (unsigned)(j * 4 + 2) * 4u, h2pack(a.z, c.z));
            sts32(vb + (unsigned)(j * 4 + 3) * 4u, h2pack(a.w, c.w));
        }
    };

    if (tcount > 0) ldg_tile(sbeg);

    float acc[16][4];
#pragma unroll
    for (int nt = 0; nt < 16; nt++)
#pragma unroll
        for (int j = 0; j < 4; j++) acc[nt][j] = 0.f;
    float m0 = -FLT_MAX, m1 = -FLT_MAX, l0 = 0.f, l1 = 0.f;

    for (int t = 0; t < tcount; t++) {
        const int s0 = sbeg + t * KV_TILE;
        const int buf = t & 1;
        sts_tile(buf);
        __syncthreads();
        if (t + 1 < tcount) ldg_tile(s0 + KV_TILE);

        const unsigned kb = sbK + (unsigned)(buf * KBUFW) * 4u;
        const unsigned vb = sbV + (unsigned)(buf * VBUFW) * 4u;

        // ---- QK^T ----
        float sc[4][4];
#pragma unroll
        for (int nt = 0; nt < 4; nt++)
#pragma unroll
            for (int j = 0; j < 4; j++) sc[nt][j] = 0.f;
#pragma unroll
        for (int ks = 0; ks < 8; ks++) {
#pragma unroll
            for (int nt = 0; nt < 4; nt++) {
                int key = nt * 8 + gid;
                unsigned bfr[2];
                lds64(bfr[0], bfr[1],
                      kb + (unsigned)(key * KROWW) * 4u + (unsigned)(ks * 32 + ctg * 8));
                mma_f16(sc[nt], qreg[ks], bfr);
            }
        }

        // ---- mask + warp-local online softmax ----
        const int p0 = pos_s[gid];
        const int p1 = pos_s[gid + 8];
        float tm0 = -FLT_MAX, tm1 = -FLT_MAX;
#pragma unroll
        for (int nt = 0; nt < 4; nt++) {
            int cb = nt * 8 + 2 * ctg;
            int sA = s0 + cb, sB = sA + 1;
            sc[nt][0] = (sA < send && sA <= p0) ? sc[nt][0] : -FLT_MAX;
            sc[nt][1] = (sB < send && sB <= p0) ? sc[nt][1] : -FLT_MAX;
            sc[nt][2] = (sA < send && sA <= p1) ? sc[nt][2] : -FLT_MAX;
            sc[nt][3] = (sB < send && sB <= p1) ? sc[nt][3] : -FLT_MAX;
            tm0 = fmaxf(tm0, fmaxf(sc[nt][0], sc[nt][1]));
            tm1 = fmaxf(tm1, fmaxf(sc[nt][2], sc[nt][3]));
        }
        tm0 = fmaxf(tm0, __shfl_xor_sync(0xFFFFFFFF, tm0, 1));
        tm0 = fmaxf(tm0, __shfl_xor_sync(0xFFFFFFFF, tm0, 2));
        tm1 = fmaxf(tm1, __shfl_xor_sync(0xFFFFFFFF, tm1, 1));
        tm1 = fmaxf(tm1, __shfl_xor_sync(0xFFFFFFFF, tm1, 2));
        float mn0 = fmaxf(m0, tm0), mn1 = fmaxf(m1, tm1);
        float scl0 = __expf(m0 - mn0), scl1 = __expf(m1 - mn1);

        unsigned ps[4][2];
        float su0 = 0.f, su1 = 0.f;
#pragma unroll
        for (int nt = 0; nt < 4; nt++) {
            float e0 = __expf(sc[nt][0] - mn0), e1 = __expf(sc[nt][1] - mn0);
            float e2 = __expf(sc[nt][2] - mn1), e3 = __expf(sc[nt][3] - mn1);
            ps[nt][0] = h2pack(e0, e1);
            ps[nt][1] = h2pack(e2, e3);
            float2 f0 = __half22float2(*reinterpret_cast<__half2*>(&ps[nt][0]));
            float2 f1 = __half22float2(*reinterpret_cast<__half2*>(&ps[nt][1]));
            su0 += f0.x + f0.y;
            su1 += f1.x + f1.y;
        }
        su0 += __shfl_xor_sync(0xFFFFFFFF, su0, 1);
        su0 += __shfl_xor_sync(0xFFFFFFFF, su0, 2);
        su1 += __shfl_xor_sync(0xFFFFFFFF, su1, 1);
        su1 += __shfl_xor_sync(0xFFFFFFFF, su1, 2);
        l0 = l0 * scl0 + su0;
        l1 = l1 * scl1 + su1;
        m0 = mn0; m1 = mn1;

        // ---- rescale ----
#pragma unroll
        for (int nt = 0; nt < 16; nt++) {
            acc[nt][0] *= scl0; acc[nt][1] *= scl0;
            acc[nt][2] *= scl1; acc[nt][3] *= scl1;
        }

        // ---- P@V ----
#pragma unroll
        for (int kt = 0; kt < 2; kt++) {
            unsigned a[4];
            a[0] = ps[2 * kt][0];
            a[1] = ps[2 * kt][1];
            a[2] = ps[2 * kt + 1][0];
            a[3] = ps[2 * kt + 1][1];
#pragma unroll
            for (int nt = 0; nt < 16; nt++) {
                int n = nt * 8 + gid;
                unsigned bfr[2];
                bfr[0] = lds32(vb + (unsigned)((8 * kt + ctg) * VROWW + n) * 4u);
                bfr[1] = lds32(vb + (unsigned)((8 * kt + ctg + 4) * VROWW + n) * 4u);
                mma_f16(acc[nt], a, bfr);
            }
        }
    }

    // ---- write split partials ----
    {
        float* pbase = g_pacc + ((size_t)split * Bq * KVq + bk) * AROWS * Dq;
#pragma unroll
        for (int nt = 0; nt < 16; nt++) {
            int col = nt * 8 + 2 * ctg;
            *reinterpret_cast<float2*>(&pbase[(size_t)r0 * Dq + col]) =
                make_float2(acc[nt][0], acc[nt][1]);
            *reinterpret_cast<float2*>(&pbase[(size_t)(r0 + 8) * Dq + col]) =
                make_float2(acc[nt][2], acc[nt][3]);
        }
    }
    if (ctg == 0) {
        int o = (split * Bq * KVq + bk) * AROWS;
        g_pm[o + r0] = m0;      g_pl[o + r0] = l0;
        g_pm[o + r0 + 8] = m1;  g_pl[o + r0 + 8] = l1;
    }
}

// ---------------- combine splits --------------------------------------------
__global__ void combine_kernel() {
    int idx = blockIdx.x * 256 + threadIdx.x;
    if (idx >= Bq * KVq * AROWS * Dq) return;
    int d = idx & 127;
    int r = (idx >> 7) & 63;
    int bk = idx >> 13;
    float M = -FLT_MAX;
#pragma unroll
    for (int sp = 0; sp < NSPLIT; sp++)
        M = fmaxf(M, g_pm[(sp * Bq * KVq + bk) * AROWS + r]);
    float L = 0.f, Y = 0.f;
#pragma unroll
    for (int sp = 0; sp < NSPLIT; sp++) {
        int o = (sp * Bq * KVq + bk) * AROWS + r;
        float w = __expf(g_pm[o] - M);
        L += g_pl[o] * w;
        Y += g_pacc[(size_t)o * Dq + d] * w;
    }
    float y = Y / L;
    int b = bk >> 3, kv = bk & 7;
    int hl = r >> 4, t = r & 15;
    int h = kv * GQ + hl;
    int m = b * Tq + t;
    g_y[(size_t)m * HD + h * Dq + d] = y;
}

// ---------------- launch -----------------------------------------------------
extern "C" void kernel_launch(void* const* d_in, const int* in_sizes, int n_in,
                              void* d_out, int out_size) {
    const float* x  = (const float*)d_in[0];
    const float* fc = (const float*)d_in[1];
    const float* fs = (const float*)d_in[2];
    const int*  pos = (const int*)  d_in[3];
    const float* kc = (const float*)d_in[5];
    const float* vc = (const float*)d_in[6];
    const float* wq = (const float*)d_in[7];
    const float* wk = (const float*)d_in[8];
    const float* wv = (const float*)d_in[9];
    const float* wo = (const float*)d_in[10];
    float* out = (float*)d_out;

    cudaFuncSetAttribute(qkv_kernel, cudaFuncAttributeMaxDynamicSharedMemorySize,
                         GEMM_SMEM_BYTES);
    cudaFuncSetAttribute(out_kernel, cudaFuncAttributeMaxDynamicSharedMemorySize,
                         GEMM_SMEM_BYTES);

    qkv_kernel<<<dim3(NTOT / 128, SPLITK), 256, GEMM_SMEM_BYTES>>>(x, wq, wk, wv);
    rope_all_kernel<<<(QPAIRS + KPAIRS + VQUADS + 255) / 256, 256>>>(fc, fs);
    // attn stays 4th launch for ncu slot continuity... (3rd now; profile may move)
    attn_kernel<<<NSPLIT * Bq * KVq, 128>>>(kc, vc, pos);
    combine_kernel<<<(Bq * KVq * AROWS * Dq + 255) / 256, 256>>>();
    out_kernel<<<dim3(DIMq / 128, SPLITKO), 256, GEMM_SMEM_BYTES>>>(wo);
    reduce_out_kernel<<<(M64 * DIMq / 4 + 255) / 256, 256>>>(out);
}